// round 10
// baseline (speedup 1.0000x reference)
#include <cuda_runtime.h>
#include <cuda_bf16.h>

// NormalsRenderer: B=512, N=512.
// out[b] = normalize( sum_i acc_i * n_i ),  acc_i = sum_{j!=i} exp(-acos(clip(<n_i,n_j>)))
// Identities (uniform positive scales cancel under the final normalize):
//   - division by max(new_weights) dropped; exp(-acos d) = const * exp(asin d)
//   - u = sat(1-|d|);  asin(|d|)*log2e = LHPI + sqrt(u)*Q(u)  (cubic Q)
//   - w = exp2( copysign( LHPI + sqrt(u)*Q(u), d ) )
// 512 rows = 16 groups of 32. The 136 unordered group-tiles are covered exactly once
// by 31 chunks (i-run of up to 6 groups x 1 j-group), 8 warps x <=4 chunks per batch,
// <=128 rotation steps per warp (R9 spent 160 incl. 15% partial-chunk waste).
// In a chunk, lane l holds one i-row per group IN REGISTERS (f32x2-packed by group
// pairs); the j-row rotates via shfl with a traveling column accumulator.
// Diagonal runtime handling: diag group is always LAST in its run; rowacc keeps the
// s=0 self term and one eval1(self) is subtracted at flush (bitwise cancel);
// colacc excludes the last group via fmaf(last, mask, ...), mask = diag ? 0 : 1.
// 2 CTAs/batch (grid 1024, 128 thr, <=72 regs for 7 CTAs/SM single wave);
// per-warp smem row accumulators, CTA reduce, cross-CTA atomic merge.

#define NPTS 512
#define TPB  128

typedef unsigned long long ull;
typedef unsigned int uint;

// -log2(e) * p_AS(1-u) re-expanded in u, and log2(e)*pi/2
#define Q0f (-2.0401824f)
#define Q1f (-0.17280645f)
#define Q2f (-0.026074023f)
#define Q3f (-0.027020667f)
#define LHPIf (2.2661800709f)

__device__ float g_stage[1024][3];
__device__ int   g_cnt[512];

// chunk tables: warp W (0..7) runs up to 4 chunks (gj, gib, ng); ng=0 = sentinel.
// Exact cover of all 136 (i<=j) group-tiles; diag iff gib+ng-1 == gj (always last).
__constant__ signed char c_gj[8][4] = {
    {0,11,11,15}, {1,9,10,7}, {2,10,13,9}, {3,14,12,7},
    {4,12,6,15},  {5,8,14,0}, {13,12,15,6}, {14,13,15,8}};
__constant__ signed char c_gib[8][4] = {
    {0,0,6,12}, {0,0,6,0}, {0,0,10,6}, {0,10,5,4},
    {0,9,0,8},  {0,3,5,0}, {0,0,4,4},  {0,5,0,0}};
__constant__ signed char c_ng[8][4] = {
    {1,6,6,4}, {2,6,5,4}, {3,6,4,4}, {4,5,4,4},
    {5,4,4,4}, {6,6,5,0}, {5,5,4,3}, {5,5,4,3}};

__device__ __forceinline__ ull pack2(float lo, float hi) {
    ull r; asm("mov.b64 %0, {%1, %2};" : "=l"(r) : "f"(lo), "f"(hi)); return r;
}
__device__ __forceinline__ void unpack2(ull v, float& lo, float& hi) {
    asm("mov.b64 {%0, %1}, %2;" : "=f"(lo), "=f"(hi) : "l"(v));
}
__device__ __forceinline__ ull fma2(ull a, ull b, ull c) {
    ull d; asm("fma.rn.f32x2 %0, %1, %2, %3;" : "=l"(d) : "l"(a), "l"(b), "l"(c)); return d;
}
__device__ __forceinline__ ull mul2(ull a, ull b) {
    ull d; asm("mul.rn.f32x2 %0, %1, %2;" : "=l"(d) : "l"(a), "l"(b)); return d;
}
__device__ __forceinline__ ull add2(ull a, ull b) {
    ull d; asm("add.rn.f32x2 %0, %1, %2;" : "=l"(d) : "l"(a), "l"(b)); return d;
}
__device__ __forceinline__ float sqrta(float x) {
    float r; asm("sqrt.approx.f32 %0, %1;" : "=f"(r) : "f"(x)); return r;
}
__device__ __forceinline__ float ex2a(float x) {
    float r; asm("ex2.approx.f32 %0, %1;" : "=f"(r) : "f"(x)); return r;
}

__device__ __forceinline__ ull eval2(ull xi2, ull yi2, ull zi2,
                                     ull jx2, ull jy2, ull jz2)
{
    const ull q3v = pack2(Q3f, Q3f), q2v = pack2(Q2f, Q2f);
    const ull q1v = pack2(Q1f, Q1f), q0v = pack2(Q0f, Q0f);
    const ull lh2 = pack2(LHPIf, LHPIf);
    ull d2 = fma2(zi2, jz2, fma2(yi2, jy2, mul2(xi2, jx2)));
    float da, db; unpack2(d2, da, db);
    float ua = __saturatef(1.0f - fabsf(da));
    float ub = __saturatef(1.0f - fabsf(db));
    float sa = sqrta(ua), sb = sqrta(ub);
    ull u2 = pack2(ua, ub);
    ull p2 = fma2(u2, q3v, q2v);
    p2 = fma2(u2, p2, q1v);
    p2 = fma2(u2, p2, q0v);
    ull g2 = fma2(pack2(sa, sb), p2, lh2);
    float ga, gb; unpack2(g2, ga, gb);
    uint ea = __float_as_uint(ga) | (__float_as_uint(da) & 0x80000000u);
    uint eb = __float_as_uint(gb) | (__float_as_uint(db) & 0x80000000u);
    return pack2(ex2a(__uint_as_float(ea)), ex2a(__uint_as_float(eb)));
}

__device__ __forceinline__ float eval1(float xi, float yi, float zi,
                                       float jx, float jy, float jz)
{
    float d = fmaf(zi, jz, fmaf(yi, jy, xi * jx));
    float u = __saturatef(1.0f - fabsf(d));
    float s = sqrta(u);
    float p = fmaf(u, Q3f, Q2f);
    p = fmaf(u, p, Q1f);
    p = fmaf(u, p, Q0f);
    float g = fmaf(s, p, LHPIf);
    uint  e = __float_as_uint(g) | (__float_as_uint(d) & 0x80000000u);
    return ex2a(__uint_as_float(e));
}

// NP packed group-pairs + optional scalar tail group. NG = 2*NP + HS.
template<int NP, bool HS>
__device__ __forceinline__ void process_chunk(const float4* __restrict__ sn4,
                                              float* __restrict__ raw,
                                              int gj, int gib, bool diag,
                                              int lane, int srcp)
{
    constexpr int NPA = (NP > 0) ? NP : 1;
    ull xi[NPA], yi[NPA], zi[NPA], ra[NPA];
    #pragma unroll
    for (int p = 0; p < NP; ++p) {
        float4 a = sn4[(gib + 2 * p)     * 32 + lane];
        float4 b = sn4[(gib + 2 * p + 1) * 32 + lane];
        xi[p] = pack2(a.x, b.x);
        yi[p] = pack2(a.y, b.y);
        zi[p] = pack2(a.z, b.z);
        ra[p] = pack2(0.0f, 0.0f);
    }
    float xs = 0.0f, ys = 0.0f, zs = 0.0f;
    if (HS) {
        float4 a = sn4[(gib + 2 * NP) * 32 + lane];
        xs = a.x; ys = a.y; zs = a.z;
    }
    float4 nj = sn4[gj * 32 + lane];
    float jx = nj.x, jy = nj.y, jz = nj.z;
    float ras = 0.0f, colacc = 0.0f;
    const float cmask = diag ? 0.0f : 1.0f;   // last group excluded from colacc if diag

    #pragma unroll 4
    for (int s = 0; s < 32; ++s) {
        ull jxx = pack2(jx, jx), jyy = pack2(jy, jy), jzz = pack2(jz, jz);
        float partial = 0.0f, last = 0.0f;
        #pragma unroll
        for (int p = 0; p < NP; ++p) {
            ull w = eval2(xi[p], yi[p], zi[p], jxx, jyy, jzz);
            ra[p] = add2(ra[p], w);
            float lo, hi; unpack2(w, lo, hi);
            if (p == NP - 1 && !HS) { partial += lo; last = hi; }
            else                    { partial += lo + hi; }
        }
        if (HS) {
            float ws = eval1(xs, ys, zs, jx, jy, jz);
            ras += ws;
            last = ws;
        }
        colacc = fmaf(last, cmask, colacc + partial);
        colacc = __shfl_sync(0xffffffffu, colacc, srcp);
        jx = __shfl_sync(0xffffffffu, jx, srcp);
        jy = __shfl_sync(0xffffffffu, jy, srcp);
        jz = __shfl_sync(0xffffffffu, jz, srcp);
    }

    // flush (this warp's private array — no races)
    #pragma unroll
    for (int p = 0; p < NP; ++p) {
        float lo, hi; unpack2(ra[p], lo, hi);
        raw[(gib + 2 * p)     * 32 + lane] += lo;
        raw[(gib + 2 * p + 1) * 32 + lane] += hi;
    }
    if (HS) raw[(gib + 2 * NP) * 32 + lane] += ras;

    float corr = colacc;   // aligned to column `lane` after 32 rotations
    if (diag) {            // remove the s=0 self term (same code path -> exact cancel)
        float4 n = sn4[gj * 32 + lane];
        corr -= eval1(n.x, n.y, n.z, n.x, n.y, n.z);
    }
    raw[gj * 32 + lane] += corr;
}

__global__ __launch_bounds__(TPB, 7)
void normals_chunk_kernel(const float* __restrict__ normals,
                          float* __restrict__ out)
{
    __shared__ float4 sn4[NPTS];          // 8 KB
    __shared__ float  rowaccW[4][NPTS];   // 8 KB per-warp row accumulators
    __shared__ float  sred[3][4];

    const int b    = blockIdx.x >> 1;
    const int half = blockIdx.x & 1;
    const int t    = threadIdx.x;
    const int lane = t & 31;
    const int wl   = t >> 5;
    const int srcp = (lane + 1) & 31;

    const float* base = normals + (size_t)b * NPTS * 3;
    #pragma unroll
    for (int r = t; r < NPTS; r += TPB)
        sn4[r] = make_float4(base[r * 3 + 0], base[r * 3 + 1], base[r * 3 + 2], 0.0f);
    #pragma unroll
    for (int idx = t; idx < 4 * NPTS; idx += TPB)
        ((float*)rowaccW)[idx] = 0.0f;
    __syncthreads();

    const int W = half * 4 + wl;          // global warp id 0..7
    float* raw = rowaccW[wl];

    #pragma unroll 1
    for (int c = 0; c < 4; ++c) {
        const int gj  = c_gj[W][c];
        const int gib = c_gib[W][c];
        const int ng  = c_ng[W][c];
        if (ng == 0) break;
        const bool dg = (gib + ng - 1 == gj);
        switch (ng) {
            case 1: process_chunk<0, true >(sn4, raw, gj, gib, dg, lane, srcp); break;
            case 2: process_chunk<1, false>(sn4, raw, gj, gib, dg, lane, srcp); break;
            case 3: process_chunk<1, true >(sn4, raw, gj, gib, dg, lane, srcp); break;
            case 4: process_chunk<2, false>(sn4, raw, gj, gib, dg, lane, srcp); break;
            case 5: process_chunk<2, true >(sn4, raw, gj, gib, dg, lane, srcp); break;
            default: process_chunk<3, false>(sn4, raw, gj, gib, dg, lane, srcp); break;
        }
    }
    __syncthreads();

    // weighted sum over rows handled by this thread
    float vx = 0.0f, vy = 0.0f, vz = 0.0f;
    #pragma unroll
    for (int r = t; r < NPTS; r += TPB) {
        float wsum = (rowaccW[0][r] + rowaccW[1][r])
                   + (rowaccW[2][r] + rowaccW[3][r]);
        float4 n = sn4[r];
        vx = fmaf(wsum, n.x, vx);
        vy = fmaf(wsum, n.y, vy);
        vz = fmaf(wsum, n.z, vz);
    }

    #pragma unroll
    for (int s = 16; s >= 1; s >>= 1) {
        vx += __shfl_down_sync(0xffffffffu, vx, s);
        vy += __shfl_down_sync(0xffffffffu, vy, s);
        vz += __shfl_down_sync(0xffffffffu, vz, s);
    }
    if (lane == 0) { sred[0][wl] = vx; sred[1][wl] = vy; sred[2][wl] = vz; }
    __syncthreads();

    if (t == 0) {
        float rx = (sred[0][0] + sred[0][1]) + (sred[0][2] + sred[0][3]);
        float ry = (sred[1][0] + sred[1][1]) + (sred[1][2] + sred[1][3]);
        float rz = (sred[2][0] + sred[2][1]) + (sred[2][2] + sred[2][3]);
        g_stage[blockIdx.x][0] = rx;
        g_stage[blockIdx.x][1] = ry;
        g_stage[blockIdx.x][2] = rz;
        __threadfence();
        int old = atomicAdd(&g_cnt[b], 1);
        if (old == 1) {
            __threadfence();
            const int other = blockIdx.x ^ 1;
            rx += g_stage[other][0];
            ry += g_stage[other][1];
            rz += g_stage[other][2];
            float ss  = fmaf(rx, rx, fmaf(ry, ry, rz * rz));
            float inv = rsqrtf(fmaxf(ss, 1e-20f));
            out[b * 3 + 0] = rx * inv;
            out[b * 3 + 1] = ry * inv;
            out[b * 3 + 2] = rz * inv;
            g_cnt[b] = 0;   // deterministic state for graph replay
        }
    }
}

extern "C" void kernel_launch(void* const* d_in, const int* in_sizes, int n_in,
                              void* d_out, int out_size)
{
    const float* normals = (const float*)d_in[0];  // [512, 512, 3] f32
    // d_in[1] = weights: unused by the reference math.
    float* out = (float*)d_out;                    // [512, 3] f32

    normals_chunk_kernel<<<1024, TPB>>>(normals, out);
}

// round 11
// speedup vs baseline: 1.0452x; 1.0452x over previous
#include <cuda_runtime.h>
#include <cuda_bf16.h>

// NormalsRenderer: B=512, N=512.
// out[b] = normalize( sum_i acc_i * n_i ),  acc_i = sum_{j!=i} exp(-acos(clip(<n_i,n_j>)))
// Identities (uniform positive scales cancel under the final normalize):
//   - division by max(new_weights) dropped; exp(-acos d) = const * exp(asin d)
//   - u = sat(1-|d|);  asin(|d|)*log2e = LHPI + sqrt(u)*Q(u)  (cubic Q)
//   - w = exp2( copysign( LHPI + sqrt(u)*Q(u), d ) )
// 512 rows = 16 groups of 32. The 136 unordered group-tiles are covered exactly once
// by 34 chunks (i-run of <=5 groups x 1 j-group): warps W0-5 get 4 chunks (128 steps),
// W6-7 get 5 (160). Lane l holds one i-row per group in registers (f32x2-packed in
// pairs + optional scalar tail); the j-row rotates via shfl with a traveling column
// accumulator. The diag group (i-run containing gj) is always LAST in its run: its
// colacc exclusion is fmaf(last, cmask, rest) — same op count as the add it replaces.
// The s=0 self term stays in rowacc and one eval1(self) is subtracted at flush
// (f32x2 lanes round identically to scalar fma -> bitwise cancel).
// 2 CTAs/batch (grid 1024, 128 thr, <=64 regs / 8 CTA residency); per-warp smem row
// accumulators, CTA reduce, cross-CTA atomic merge (second finisher normalizes).

#define NPTS 512
#define TPB  128

typedef unsigned long long ull;
typedef unsigned int uint;

// -log2(e) * p_AS(1-u) re-expanded in u, and log2(e)*pi/2
#define Q0f (-2.0401824f)
#define Q1f (-0.17280645f)
#define Q2f (-0.026074023f)
#define Q3f (-0.027020667f)
#define LHPIf (2.2661800709f)

__device__ float g_stage[1024][3];
__device__ int   g_cnt[512];

// chunk tables: warp W (0..7) runs up to 5 chunks (gj, gib, ng); ng=0 sentinel.
// Exact cover of all 136 (i<=j) group-tiles; diag iff gib+ng-1 == gj (always last).
__constant__ signed char c_gj[8][5] = {
    {4,6,3,2,-1}, {7,8,8,5,-1}, {9,9,13,5,-1}, {10,10,11,1,-1},
    {11,12,12,6,-1}, {13,13,14,11,-1}, {14,14,7,12,0}, {15,15,15,10,15}};
__constant__ signed char c_gib[8][5] = {
    {0,0,0,0,0}, {0,0,5,0,0}, {0,5,10,3,0}, {0,5,0,0,0},
    {5,0,5,5,0}, {0,5,0,10,0}, {5,10,5,10,0}, {0,5,10,10,15}};
__constant__ signed char c_ng[8][5] = {
    {5,5,4,3,0}, {5,5,4,3,0}, {5,5,4,3,0}, {5,5,5,2,0},
    {5,5,5,2,0}, {5,5,5,2,0}, {5,5,3,3,1}, {5,5,5,1,1}};

__device__ __forceinline__ ull pack2(float lo, float hi) {
    ull r; asm("mov.b64 %0, {%1, %2};" : "=l"(r) : "f"(lo), "f"(hi)); return r;
}
__device__ __forceinline__ void unpack2(ull v, float& lo, float& hi) {
    asm("mov.b64 {%0, %1}, %2;" : "=f"(lo), "=f"(hi) : "l"(v));
}
__device__ __forceinline__ ull fma2(ull a, ull b, ull c) {
    ull d; asm("fma.rn.f32x2 %0, %1, %2, %3;" : "=l"(d) : "l"(a), "l"(b), "l"(c)); return d;
}
__device__ __forceinline__ ull mul2(ull a, ull b) {
    ull d; asm("mul.rn.f32x2 %0, %1, %2;" : "=l"(d) : "l"(a), "l"(b)); return d;
}
__device__ __forceinline__ ull add2(ull a, ull b) {
    ull d; asm("add.rn.f32x2 %0, %1, %2;" : "=l"(d) : "l"(a), "l"(b)); return d;
}
__device__ __forceinline__ float sqrta(float x) {
    float r; asm("sqrt.approx.f32 %0, %1;" : "=f"(r) : "f"(x)); return r;
}
__device__ __forceinline__ float ex2a(float x) {
    float r; asm("ex2.approx.f32 %0, %1;" : "=f"(r) : "f"(x)); return r;
}

__device__ __forceinline__ ull eval2(ull xi2, ull yi2, ull zi2,
                                     ull jx2, ull jy2, ull jz2)
{
    const ull q3v = pack2(Q3f, Q3f), q2v = pack2(Q2f, Q2f);
    const ull q1v = pack2(Q1f, Q1f), q0v = pack2(Q0f, Q0f);
    const ull lh2 = pack2(LHPIf, LHPIf);
    ull d2 = fma2(zi2, jz2, fma2(yi2, jy2, mul2(xi2, jx2)));
    float da, db; unpack2(d2, da, db);
    float ua = __saturatef(1.0f - fabsf(da));
    float ub = __saturatef(1.0f - fabsf(db));
    float sa = sqrta(ua), sb = sqrta(ub);
    ull u2 = pack2(ua, ub);
    ull p2 = fma2(u2, q3v, q2v);
    p2 = fma2(u2, p2, q1v);
    p2 = fma2(u2, p2, q0v);
    ull g2 = fma2(pack2(sa, sb), p2, lh2);
    float ga, gb; unpack2(g2, ga, gb);
    uint ea = __float_as_uint(ga) | (__float_as_uint(da) & 0x80000000u);
    uint eb = __float_as_uint(gb) | (__float_as_uint(db) & 0x80000000u);
    return pack2(ex2a(__uint_as_float(ea)), ex2a(__uint_as_float(eb)));
}

__device__ __forceinline__ float eval1(float xi, float yi, float zi,
                                       float jx, float jy, float jz)
{
    float d = fmaf(zi, jz, fmaf(yi, jy, xi * jx));
    float u = __saturatef(1.0f - fabsf(d));
    float s = sqrta(u);
    float p = fmaf(u, Q3f, Q2f);
    p = fmaf(u, p, Q1f);
    p = fmaf(u, p, Q0f);
    float g = fmaf(s, p, LHPIf);
    uint  e = __float_as_uint(g) | (__float_as_uint(d) & 0x80000000u);
    return ex2a(__uint_as_float(e));
}

// NP packed group-pairs + optional scalar tail. NG = 2*NP + HS. Diag group = last.
template<int NP, bool HS>
__device__ __forceinline__ void process_chunk(const float4* __restrict__ sn4,
                                              float* __restrict__ raw,
                                              int gj, int gib, bool diag,
                                              int lane, int srcp)
{
    constexpr int NPA = (NP > 0) ? NP : 1;
    ull xi[NPA], yi[NPA], zi[NPA], ra[NPA];
    #pragma unroll
    for (int p = 0; p < NP; ++p) {
        float4 a = sn4[(gib + 2 * p)     * 32 + lane];
        float4 b = sn4[(gib + 2 * p + 1) * 32 + lane];
        xi[p] = pack2(a.x, b.x);
        yi[p] = pack2(a.y, b.y);
        zi[p] = pack2(a.z, b.z);
        ra[p] = pack2(0.0f, 0.0f);
    }
    float xs = 0.0f, ys = 0.0f, zs = 0.0f, ras = 0.0f;
    if (HS) {
        float4 a = sn4[(gib + 2 * NP) * 32 + lane];
        xs = a.x; ys = a.y; zs = a.z;
    }
    float4 nj = sn4[gj * 32 + lane];
    float jx = nj.x, jy = nj.y, jz = nj.z;
    float colacc = 0.0f;
    const float cmask = diag ? 0.0f : 1.0f;   // last group excluded from colacc if diag

    #pragma unroll 4
    for (int s = 0; s < 32; ++s) {
        ull jxx = pack2(jx, jx), jyy = pack2(jy, jy), jzz = pack2(jz, jz);
        float rest = 0.0f, lastval;
        if (NP >= 1) {
            ull w0 = eval2(xi[0], yi[0], zi[0], jxx, jyy, jzz);
            ra[0] = add2(ra[0], w0);
            float a0, b0; unpack2(w0, a0, b0);
            if (NP == 1 && !HS) { rest = a0; lastval = b0; }
            else                  rest = a0 + b0;
        }
        if (NP == 2) {
            ull w1 = eval2(xi[1], yi[1], zi[1], jxx, jyy, jzz);
            ra[1] = add2(ra[1], w1);
            float a1, b1; unpack2(w1, a1, b1);
            if (!HS) { rest += a1; lastval = b1; }
            else       rest += a1 + b1;
        }
        if (HS) {
            float ws = eval1(xs, ys, zs, jx, jy, jz);
            ras += ws;
            lastval = ws;
        }
        colacc = fmaf(lastval, cmask, colacc + rest);
        colacc = __shfl_sync(0xffffffffu, colacc, srcp);
        jx = __shfl_sync(0xffffffffu, jx, srcp);
        jy = __shfl_sync(0xffffffffu, jy, srcp);
        jz = __shfl_sync(0xffffffffu, jz, srcp);
    }

    // Diag correction: s=0 computed the self pair through the same rounding path
    // (f32x2 lanes == scalar fma.rn); subtract it from the diag (= last) group's row.
    float selfw = 0.0f;
    if (diag) {
        float4 n = sn4[gj * 32 + lane];
        selfw = eval1(n.x, n.y, n.z, n.x, n.y, n.z);
    }

    // flush (this warp's private array — no races)
    #pragma unroll
    for (int p = 0; p < NP; ++p) {
        float lo, hi; unpack2(ra[p], lo, hi);
        raw[(gib + 2 * p) * 32 + lane] += lo;
        if (!HS && p == NP - 1) hi -= selfw;
        raw[(gib + 2 * p + 1) * 32 + lane] += hi;
    }
    if (HS) raw[(gib + 2 * NP) * 32 + lane] += ras - selfw;
    raw[gj * 32 + lane] += colacc;   // aligned to column `lane` after 32 rotations
}

__global__ __launch_bounds__(TPB, 8)
void normals_chunk_kernel(const float* __restrict__ normals,
                          float* __restrict__ out)
{
    __shared__ float4 sn4[NPTS];          // 8 KB
    __shared__ float  rowaccW[4][NPTS];   // 8 KB per-warp row accumulators
    __shared__ float  sred[3][4];

    const int b    = blockIdx.x >> 1;
    const int half = blockIdx.x & 1;
    const int t    = threadIdx.x;
    const int lane = t & 31;
    const int wl   = t >> 5;
    const int srcp = (lane + 1) & 31;

    const float* base = normals + (size_t)b * NPTS * 3;
    #pragma unroll
    for (int r = t; r < NPTS; r += TPB)
        sn4[r] = make_float4(base[r * 3 + 0], base[r * 3 + 1], base[r * 3 + 2], 0.0f);
    #pragma unroll
    for (int idx = t; idx < 4 * NPTS; idx += TPB)
        ((float*)rowaccW)[idx] = 0.0f;
    __syncthreads();

    const int W = half * 4 + wl;          // global warp id 0..7
    float* raw = rowaccW[wl];

    #pragma unroll 1
    for (int c = 0; c < 5; ++c) {
        const int ng = c_ng[W][c];
        if (ng == 0) break;
        const int gj  = c_gj[W][c];
        const int gib = c_gib[W][c];
        const bool dg = (gib + ng - 1 == gj);
        switch (ng) {
            case 5: process_chunk<2, true >(sn4, raw, gj, gib, dg, lane, srcp); break;
            case 4: process_chunk<2, false>(sn4, raw, gj, gib, dg, lane, srcp); break;
            case 3: process_chunk<1, true >(sn4, raw, gj, gib, dg, lane, srcp); break;
            case 2: process_chunk<1, false>(sn4, raw, gj, gib, dg, lane, srcp); break;
            default: process_chunk<0, true >(sn4, raw, gj, gib, dg, lane, srcp); break;
        }
    }
    __syncthreads();

    // weighted sum over rows handled by this thread
    float vx = 0.0f, vy = 0.0f, vz = 0.0f;
    #pragma unroll
    for (int r = t; r < NPTS; r += TPB) {
        float wsum = (rowaccW[0][r] + rowaccW[1][r])
                   + (rowaccW[2][r] + rowaccW[3][r]);
        float4 n = sn4[r];
        vx = fmaf(wsum, n.x, vx);
        vy = fmaf(wsum, n.y, vy);
        vz = fmaf(wsum, n.z, vz);
    }

    #pragma unroll
    for (int s = 16; s >= 1; s >>= 1) {
        vx += __shfl_down_sync(0xffffffffu, vx, s);
        vy += __shfl_down_sync(0xffffffffu, vy, s);
        vz += __shfl_down_sync(0xffffffffu, vz, s);
    }
    if (lane == 0) { sred[0][wl] = vx; sred[1][wl] = vy; sred[2][wl] = vz; }
    __syncthreads();

    if (t == 0) {
        float rx = (sred[0][0] + sred[0][1]) + (sred[0][2] + sred[0][3]);
        float ry = (sred[1][0] + sred[1][1]) + (sred[1][2] + sred[1][3]);
        float rz = (sred[2][0] + sred[2][1]) + (sred[2][2] + sred[2][3]);
        g_stage[blockIdx.x][0] = rx;
        g_stage[blockIdx.x][1] = ry;
        g_stage[blockIdx.x][2] = rz;
        __threadfence();
        int old = atomicAdd(&g_cnt[b], 1);
        if (old == 1) {
            __threadfence();
            const int other = blockIdx.x ^ 1;
            rx += g_stage[other][0];
            ry += g_stage[other][1];
            rz += g_stage[other][2];
            float ss  = fmaf(rx, rx, fmaf(ry, ry, rz * rz));
            float inv = rsqrtf(fmaxf(ss, 1e-20f));
            out[b * 3 + 0] = rx * inv;
            out[b * 3 + 1] = ry * inv;
            out[b * 3 + 2] = rz * inv;
            g_cnt[b] = 0;   // deterministic state for graph replay
        }
    }
}

extern "C" void kernel_launch(void* const* d_in, const int* in_sizes, int n_in,
                              void* d_out, int out_size)
{
    const float* normals = (const float*)d_in[0];  // [512, 512, 3] f32
    // d_in[1] = weights: unused by the reference math.
    float* out = (float*)d_out;                    // [512, 3] f32

    normals_chunk_kernel<<<1024, TPB>>>(normals, out);
}